// round 5
// baseline (speedup 1.0000x reference)
#include <cuda_runtime.h>
#include <math.h>

// ---------------- problem constants ----------------
#define BB   2
#define SS   2048
#define DD   1024
#define HH   16
#define DHH  64
#define MLPD 4096
#define ROWS (BB*SS)          // 4096 tokens
#define CCH  128              // attention chunk length
#define NCH  (SS/CCH)         // 16 chunks per sequence
#define BHN  (BB*HH)          // 32 (b,h) pairs
#define NCHUNKS_TOT (BHN*NCH) // 512

// ---------------- scratch (device globals; no allocation allowed) ----------------
__device__ float g_xln [ROWS*DD];
__device__ float g_q   [ROWS*DD];
__device__ float g_k   [ROWS*DD];
__device__ float g_v   [ROWS*DD];
__device__ float g_attn[ROWS*DD];
__device__ float g_x2  [ROWS*DD];
__device__ float g_yln [ROWS*DD];
__device__ float g_h1  [ROWS*MLPD];
__device__ float g_ckv  [NCHUNKS_TOT*DHH*DHH];
__device__ float g_cks  [NCHUNKS_TOT*DHH];
__device__ float g_kvpre[NCHUNKS_TOT*DHH*DHH];
__device__ float g_kspre[NCHUNKS_TOT*DHH];

typedef unsigned long long u64;

// packed f32x2 helpers (Blackwell sm_103a)
__device__ __forceinline__ u64 pk2(float lo, float hi) {
    u64 r;
    asm("mov.b64 %0, {%1, %2};" : "=l"(r)
        : "r"(__float_as_uint(lo)), "r"(__float_as_uint(hi)));
    return r;
}
__device__ __forceinline__ u64 fma2(u64 a, u64 b, u64 c) {
    u64 d;
    asm("fma.rn.f32x2 %0, %1, %2, %3;" : "=l"(d) : "l"(a), "l"(b), "l"(c));
    return d;
}
__device__ __forceinline__ void upk2(u64 v, float& lo, float& hi) {
    unsigned int a, b;
    asm("mov.b64 {%0, %1}, %2;" : "=r"(a), "=r"(b) : "l"(v));
    lo = __uint_as_float(a);
    hi = __uint_as_float(b);
}

__device__ __forceinline__ float gelu_t(float x) {
    // jax.nn.gelu default: tanh approximation
    float x3 = x * x * x;
    float t = tanhf(0.7978845608028654f * (x + 0.044715f * x3));
    return 0.5f * x * (1.0f + t);
}

// ---------------- LayerNorm: one block per row ----------------
__global__ void __launch_bounds__(256)
ln_kernel(const float* __restrict__ x, const float* __restrict__ sc,
          const float* __restrict__ bi, float* __restrict__ y)
{
    int row = blockIdx.x;
    int t = threadIdx.x;
    const float4* xr = (const float4*)(x + (size_t)row * DD);
    float4 v = xr[t];
    float s  = v.x + v.y + v.z + v.w;
    float ss = v.x*v.x + v.y*v.y + v.z*v.z + v.w*v.w;
#pragma unroll
    for (int o = 16; o > 0; o >>= 1) {
        s  += __shfl_xor_sync(0xffffffffu, s,  o);
        ss += __shfl_xor_sync(0xffffffffu, ss, o);
    }
    __shared__ float sh[16];
    int w = t >> 5, l = t & 31;
    if (l == 0) { sh[w] = s; sh[8 + w] = ss; }
    __syncthreads();
    if (t < 32) {
        s  = (t < 8) ? sh[t]     : 0.f;
        ss = (t < 8) ? sh[8 + t] : 0.f;
#pragma unroll
        for (int o = 4; o > 0; o >>= 1) {
            s  += __shfl_xor_sync(0xffffffffu, s,  o);
            ss += __shfl_xor_sync(0xffffffffu, ss, o);
        }
        if (t == 0) { sh[0] = s; sh[8] = ss; }
    }
    __syncthreads();
    float mean = sh[0] * (1.0f / (float)DD);
    float var  = sh[8] * (1.0f / (float)DD) - mean * mean;
    float rs = rsqrtf(var + 1e-6f);
    float4 scv = ((const float4*)sc)[t];
    float4 biv = ((const float4*)bi)[t];
    float4 o;
    o.x = (v.x - mean) * rs * scv.x + biv.x;
    o.y = (v.y - mean) * rs * scv.y + biv.y;
    o.z = (v.z - mean) * rs * scv.z + biv.z;
    o.w = (v.w - mean) * rs * scv.w + biv.w;
    ((float4*)(y + (size_t)row * DD))[t] = o;
}

// ---------------- fp32 GEMM, 128x128x8 tile, f32x2 packed FMAs ----------------
// EPI: 0 = none, 1 = relu+eps (phi), 2 = +residual, 3 = +bias then gelu, 4 = +bias +residual
template <int EPI>
__global__ void __launch_bounds__(256, 2)
gemm_kernel(const float* __restrict__ A, const float* __restrict__ B,
            float* __restrict__ C, int M, int N, int K,
            const float* __restrict__ bias, const float* __restrict__ res)
{
    __shared__ float As[2][8][128];
    __shared__ float Bs[2][8][128];

    int tid = threadIdx.x;
    int mBase = blockIdx.y * 128;
    int nBase = blockIdx.x * 128;

    int arow = tid >> 1;
    int acol = (tid & 1) * 4;
    const float* Ap = A + (size_t)(mBase + arow) * K + acol;
    int brow = tid >> 5;
    int bcol = (tid & 31) * 4;
    const float* Bp = B + (size_t)brow * N + nBase + bcol;

    float4 ra = *(const float4*)Ap;
    float4 rb = *(const float4*)Bp;
    As[0][acol + 0][arow] = ra.x;
    As[0][acol + 1][arow] = ra.y;
    As[0][acol + 2][arow] = ra.z;
    As[0][acol + 3][arow] = ra.w;
    *(float4*)&Bs[0][brow][bcol] = rb;
    __syncthreads();

    int ty = tid >> 4, tx = tid & 15;
    u64 acc[8][4];
#pragma unroll
    for (int i = 0; i < 8; i++)
#pragma unroll
        for (int j = 0; j < 4; j++) acc[i][j] = 0ull;  // bits of (0.f,0.f)

    int KT = K >> 3;
    int buf = 0;
    for (int kt = 0; kt < KT; ++kt) {
        if (kt + 1 < KT) {
            ra = *(const float4*)(Ap + (kt + 1) * 8);
            rb = *(const float4*)(Bp + (size_t)(kt + 1) * 8 * N);
        }
#pragma unroll
        for (int k = 0; k < 8; k++) {
            float4 a0 = *(const float4*)&As[buf][k][ty * 8];
            float4 a1 = *(const float4*)&As[buf][k][ty * 8 + 4];
            float4 b0 = *(const float4*)&Bs[buf][k][tx * 8];
            float4 b1 = *(const float4*)&Bs[buf][k][tx * 8 + 4];
            u64 bp[4] = { pk2(b0.x, b0.y), pk2(b0.z, b0.w),
                          pk2(b1.x, b1.y), pk2(b1.z, b1.w) };
            float av[8] = { a0.x, a0.y, a0.z, a0.w, a1.x, a1.y, a1.z, a1.w };
#pragma unroll
            for (int i = 0; i < 8; i++) {
                u64 ap = pk2(av[i], av[i]);
#pragma unroll
                for (int j = 0; j < 4; j++) acc[i][j] = fma2(ap, bp[j], acc[i][j]);
            }
        }
        if (kt + 1 < KT) {
            As[buf ^ 1][acol + 0][arow] = ra.x;
            As[buf ^ 1][acol + 1][arow] = ra.y;
            As[buf ^ 1][acol + 2][arow] = ra.z;
            As[buf ^ 1][acol + 3][arow] = ra.w;
            *(float4*)&Bs[buf ^ 1][brow][bcol] = rb;
        }
        __syncthreads();
        buf ^= 1;
    }

    // epilogue
#pragma unroll
    for (int i = 0; i < 8; i++) {
        int row = mBase + ty * 8 + i;
        int col0 = nBase + tx * 8;
        float o[8];
#pragma unroll
        for (int j = 0; j < 4; j++) upk2(acc[i][j], o[2 * j], o[2 * j + 1]);

        if (EPI == 1) {
#pragma unroll
            for (int jj = 0; jj < 8; jj++) o[jj] = fmaxf(o[jj], 0.0f) + 1e-3f;
        } else if (EPI == 2) {
            const float* rp = res + (size_t)row * N + col0;
            float4 r0 = *(const float4*)rp;
            float4 r1 = *(const float4*)(rp + 4);
            o[0] += r0.x; o[1] += r0.y; o[2] += r0.z; o[3] += r0.w;
            o[4] += r1.x; o[5] += r1.y; o[6] += r1.z; o[7] += r1.w;
        } else if (EPI == 3) {
            float4 bb0 = *(const float4*)(bias + col0);
            float4 bb1 = *(const float4*)(bias + col0 + 4);
            o[0] = gelu_t(o[0] + bb0.x); o[1] = gelu_t(o[1] + bb0.y);
            o[2] = gelu_t(o[2] + bb0.z); o[3] = gelu_t(o[3] + bb0.w);
            o[4] = gelu_t(o[4] + bb1.x); o[5] = gelu_t(o[5] + bb1.y);
            o[6] = gelu_t(o[6] + bb1.z); o[7] = gelu_t(o[7] + bb1.w);
        } else if (EPI == 4) {
            float4 bb0 = *(const float4*)(bias + col0);
            float4 bb1 = *(const float4*)(bias + col0 + 4);
            const float* rp = res + (size_t)row * N + col0;
            float4 r0 = *(const float4*)rp;
            float4 r1 = *(const float4*)(rp + 4);
            o[0] += bb0.x + r0.x; o[1] += bb0.y + r0.y;
            o[2] += bb0.z + r0.z; o[3] += bb0.w + r0.w;
            o[4] += bb1.x + r1.x; o[5] += bb1.y + r1.y;
            o[6] += bb1.z + r1.z; o[7] += bb1.w + r1.w;
        }

        float* Cp = C + (size_t)row * N + col0;
        *(float4*)Cp       = make_float4(o[0], o[1], o[2], o[3]);
        *(float4*)(Cp + 4) = make_float4(o[4], o[5], o[6], o[7]);
    }
}

// ---------------- attention pass A: per-chunk KV = phiK^T V and ksum ----------------
__global__ void __launch_bounds__(256)
attn_chunk_kernel(const float* __restrict__ Kk, const float* __restrict__ V,
                  float* __restrict__ ckv, float* __restrict__ cks)
{
    __shared__ float sK[64][64];
    __shared__ float sV[64][64];
    int g = blockIdx.x;                // ((b*H+h)*NCH + c)
    int c = g & 15, bh = g >> 4;
    int h = bh & 15, b = bh >> 4;
    int row0 = b * SS + c * CCH;
    int colBase = h * 64;
    int t = threadIdx.x;
    int m = t >> 2;
    int d0 = (t & 3) * 16;

    float acc[16];
#pragma unroll
    for (int w = 0; w < 16; w++) acc[w] = 0.f;
    float ks = 0.f;

    for (int half = 0; half < 2; ++half) {
#pragma unroll
        for (int r = 0; r < 16; r++) {
            int e = t + 256 * r;
            int s = e >> 6, d = e & 63;
            size_t gi = (size_t)(row0 + half * 64 + s) * DD + colBase + d;
            sK[s][d] = Kk[gi];
            sV[s][d] = V[gi];
        }
        __syncthreads();
        for (int s = 0; s < 64; s++) {
            float kk = sK[s][m];
            if ((t & 3) == 0) ks += kk;
            const float* vr = &sV[s][d0];
#pragma unroll
            for (int w = 0; w < 4; w++) {
                float4 vv = *(const float4*)(vr + 4 * w);
                acc[4 * w + 0] += kk * vv.x;
                acc[4 * w + 1] += kk * vv.y;
                acc[4 * w + 2] += kk * vv.z;
                acc[4 * w + 3] += kk * vv.w;
            }
        }
        __syncthreads();
    }
    float* op = ckv + (size_t)g * (DHH * DHH) + m * 64 + d0;
#pragma unroll
    for (int w = 0; w < 4; w++)
        *(float4*)(op + 4 * w) = make_float4(acc[4*w], acc[4*w+1], acc[4*w+2], acc[4*w+3]);
    if ((t & 3) == 0) cks[g * 64 + m] = ks;
}

// ---------------- attention pass B: exclusive prefix over chunks ----------------
__global__ void __launch_bounds__(256)
attn_scan_kernel(const float* __restrict__ ckv, const float* __restrict__ cks,
                 float* __restrict__ kvpre, float* __restrict__ kspre)
{
    int bh = blockIdx.x;
    int t = threadIdx.x;
    float run[16];
#pragma unroll
    for (int r = 0; r < 16; r++) run[r] = 0.f;
    float krun = 0.f;
    for (int c = 0; c < NCH; c++) {
        size_t base = ((size_t)bh * NCH + c) * (DHH * DHH);
#pragma unroll
        for (int r = 0; r < 16; r++) {
            int e = t + 256 * r;
            kvpre[base + e] = run[r];
            run[r] += ckv[base + e];
        }
        if (t < 64) {
            int kb = (bh * NCH + c) * 64 + t;
            kspre[kb] = krun;
            krun += cks[kb];
        }
    }
}

// ---------------- attention pass C: per-chunk causal output ----------------
// dyn smem layout (floats): sQt[64][132], sKt[64][132], sV[128][68], sKV[64][68], sKs[64], sA[128][132]
#define ATTN_SMEM_FLOATS (64*132 + 64*132 + 128*68 + 64*68 + 64 + 128*132)
#define ATTN_SMEM_BYTES  (ATTN_SMEM_FLOATS * 4)

__global__ void __launch_bounds__(256)
attn_out_kernel(const float* __restrict__ Q, const float* __restrict__ Kk,
                const float* __restrict__ V, const float* __restrict__ kvpre,
                const float* __restrict__ kspre, float* __restrict__ attn)
{
    extern __shared__ float sm[];
    float* sQt = sm;                       // [64][132] (m-major, transposed)
    float* sKt = sQt + 64 * 132;           // [64][132]
    float* sV  = sKt + 64 * 132;           // [128][68]
    float* sKV = sV  + 128 * 68;           // [64][68]
    float* sKs = sKV + 64 * 68;            // [64]
    float* sA  = sKs + 64;                 // [128][132]

    int g = blockIdx.x;
    int c = g & 15, bh = g >> 4;
    int h = bh & 15, b = bh >> 4;
    int row0 = b * SS + c * CCH;
    int colBase = h * 64;
    int t = threadIdx.x;

#pragma unroll
    for (int r = 0; r < 32; r++) {
        int e = t + 256 * r;               // 0..8191
        int s = e >> 6, m = e & 63;
        size_t gi = (size_t)(row0 + s) * DD + colBase + m;
        sQt[m * 132 + s] = Q[gi];
        sKt[m * 132 + s] = Kk[gi];
        sV[s * 68 + m]   = V[gi];
    }
#pragma unroll
    for (int r = 0; r < 16; r++) {
        int e = t + 256 * r;               // 0..4095
        sKV[(e >> 6) * 68 + (e & 63)] = kvpre[(size_t)g * (DHH * DHH) + e];
    }
    if (t < 64) sKs[t] = kspre[g * 64 + t];
    __syncthreads();

    // A = phiQ @ phiK^T  (128x128), causal-masked into sA
    {
        int ty = t >> 4, tx = t & 15;
        float accA[8][8];
#pragma unroll
        for (int i = 0; i < 8; i++)
#pragma unroll
            for (int j = 0; j < 8; j++) accA[i][j] = 0.f;
        for (int kk = 0; kk < 64; kk++) {
            const float* qr = &sQt[kk * 132 + ty * 8];
            float4 q0 = *(const float4*)qr;
            float4 q1 = *(const float4*)(qr + 4);
            const float* kr = &sKt[kk * 132 + tx * 8];
            float4 k0 = *(const float4*)kr;
            float4 k1 = *(const float4*)(kr + 4);
            float qa[8] = { q0.x, q0.y, q0.z, q0.w, q1.x, q1.y, q1.z, q1.w };
            float kb[8] = { k0.x, k0.y, k0.z, k0.w, k1.x, k1.y, k1.z, k1.w };
#pragma unroll
            for (int i = 0; i < 8; i++)
#pragma unroll
                for (int j = 0; j < 8; j++) accA[i][j] += qa[i] * kb[j];
        }
        int i0 = ty * 8, j0 = tx * 8;
#pragma unroll
        for (int i = 0; i < 8; i++)
#pragma unroll
            for (int j = 0; j < 8; j++)
                sA[(i0 + i) * 132 + (j0 + j)] = (j0 + j <= i0 + i) ? accA[i][j] : 0.f;
    }
    __syncthreads();

    // out[i][d] = (sum_j A[i][j] V[j][d] + sum_m phiQ[i][m] KVpre[m][d]) / den[i]
    {
        int i = t >> 1;
        int d0 = (t & 1) * 32;
        float acc[32];
#pragma unroll
        for (int w = 0; w < 32; w++) acc[w] = 0.f;
        float den = 0.f;
        for (int j = 0; j < 128; j++) {
            float a = sA[i * 132 + j];
            den += a;
            const float* vr = &sV[j * 68 + d0];
#pragma unroll
            for (int w = 0; w < 8; w++) {
                float4 vv = *(const float4*)(vr + 4 * w);
                acc[4 * w + 0] += a * vv.x;
                acc[4 * w + 1] += a * vv.y;
                acc[4 * w + 2] += a * vv.z;
                acc[4 * w + 3] += a * vv.w;
            }
        }
        for (int m = 0; m < 64; m++) {
            float p = sQt[m * 132 + i];
            den += p * sKs[m];
            const float* kr = &sKV[m * 68 + d0];
#pragma unroll
            for (int w = 0; w < 8; w++) {
                float4 vv = *(const float4*)(kr + 4 * w);
                acc[4 * w + 0] += p * vv.x;
                acc[4 * w + 1] += p * vv.y;
                acc[4 * w + 2] += p * vv.z;
                acc[4 * w + 3] += p * vv.w;
            }
        }
        float inv = 1.0f / den;
        float* op = attn + (size_t)(row0 + i) * DD + colBase + d0;
#pragma unroll
        for (int w = 0; w < 8; w++)
            *(float4*)(op + 4 * w) = make_float4(acc[4*w] * inv, acc[4*w+1] * inv,
                                                 acc[4*w+2] * inv, acc[4*w+3] * inv);
    }
}

// ---------------- launch ----------------
extern "C" void kernel_launch(void* const* d_in, const int* in_sizes, int n_in,
                              void* d_out, int out_size)
{
    const float* inputs = (const float*)d_in[0];
    const float* ln1s   = (const float*)d_in[1];
    const float* ln1b   = (const float*)d_in[2];
    const float* wq     = (const float*)d_in[3];
    const float* wk     = (const float*)d_in[4];
    const float* wv     = (const float*)d_in[5];
    const float* wo     = (const float*)d_in[6];
    const float* ln2s   = (const float*)d_in[7];
    const float* ln2b   = (const float*)d_in[8];
    const float* w1     = (const float*)d_in[9];
    const float* b1     = (const float*)d_in[10];
    const float* w2     = (const float*)d_in[11];
    const float* b2     = (const float*)d_in[12];
    float* out = (float*)d_out;

    float *xln, *q, *k, *v, *attn, *x2, *yln, *h1, *ckv, *cks, *kvpre, *kspre;
    cudaGetSymbolAddress((void**)&xln,   g_xln);
    cudaGetSymbolAddress((void**)&q,     g_q);
    cudaGetSymbolAddress((void**)&k,     g_k);
    cudaGetSymbolAddress((void**)&v,     g_v);
    cudaGetSymbolAddress((void**)&attn,  g_attn);
    cudaGetSymbolAddress((void**)&x2,    g_x2);
    cudaGetSymbolAddress((void**)&yln,   g_yln);
    cudaGetSymbolAddress((void**)&h1,    g_h1);
    cudaGetSymbolAddress((void**)&ckv,   g_ckv);
    cudaGetSymbolAddress((void**)&cks,   g_cks);
    cudaGetSymbolAddress((void**)&kvpre, g_kvpre);
    cudaGetSymbolAddress((void**)&kspre, g_kspre);

    cudaFuncSetAttribute(attn_out_kernel,
                         cudaFuncAttributeMaxDynamicSharedMemorySize, ATTN_SMEM_BYTES);

    // 1) LN1
    ln_kernel<<<ROWS, 256>>>(inputs, ln1s, ln1b, xln);
    // 2) QKV projections (phi = relu + eps fused into Q and K epilogues)
    gemm_kernel<1><<<dim3(DD / 128, ROWS / 128), 256>>>(xln, wq, q, ROWS, DD, DD, nullptr, nullptr);
    gemm_kernel<1><<<dim3(DD / 128, ROWS / 128), 256>>>(xln, wk, k, ROWS, DD, DD, nullptr, nullptr);
    gemm_kernel<0><<<dim3(DD / 128, ROWS / 128), 256>>>(xln, wv, v, ROWS, DD, DD, nullptr, nullptr);
    // 3) chunked causal linear attention
    attn_chunk_kernel<<<NCHUNKS_TOT, 256>>>(k, v, ckv, cks);
    attn_scan_kernel<<<BHN, 256>>>(ckv, cks, kvpre, kspre);
    attn_out_kernel<<<NCHUNKS_TOT, 256, ATTN_SMEM_BYTES>>>(q, k, v, kvpre, kspre, attn);
    // 4) output projection + residual -> x2
    gemm_kernel<2><<<dim3(DD / 128, ROWS / 128), 256>>>(attn, wo, x2, ROWS, DD, DD, nullptr, inputs);
    // 5) LN2
    ln_kernel<<<ROWS, 256>>>(x2, ln2s, ln2b, yln);
    // 6) MLP
    gemm_kernel<3><<<dim3(MLPD / 128, ROWS / 128), 256>>>(yln, w1, h1, ROWS, MLPD, DD, b1, nullptr);
    gemm_kernel<4><<<dim3(DD / 128, ROWS / 128), 256>>>(h1, w2, out, ROWS, DD, MLPD, b2, x2);
}

// round 9
// speedup vs baseline: 2.2353x; 2.2353x over previous
#include <cuda_runtime.h>
#include <cuda_bf16.h>
#include <math.h>
#include <stdint.h>

// ---------------- problem constants ----------------
#define BB   2
#define SS   2048
#define DD   1024
#define HH   16
#define DHH  64
#define MLPD 4096
#define ROWS (BB*SS)          // 4096 tokens
#define CCH  128              // attention chunk length
#define NCH  (SS/CCH)         // 16 chunks per sequence
#define BHN  (BB*HH)          // 32 (b,h) pairs
#define NCHUNKS_TOT (BHN*NCH) // 512

typedef __nv_bfloat16 bf16;

// ---------------- scratch (device globals; no allocation allowed) ----------------
__device__ float g_q   [ROWS*DD];
__device__ float g_k   [ROWS*DD];
__device__ float g_v   [ROWS*DD];
__device__ float g_x2  [ROWS*DD];
__device__ bf16 g_xh[ROWS*DD],  g_xl[ROWS*DD];
__device__ bf16 g_ah[ROWS*DD],  g_al[ROWS*DD];
__device__ bf16 g_yh[ROWS*DD],  g_yl[ROWS*DD];
__device__ bf16 g_h1h[ROWS*MLPD], g_h1l[ROWS*MLPD];
__device__ bf16 g_wqt_h[DD*DD],  g_wqt_l[DD*DD];
__device__ bf16 g_wkt_h[DD*DD],  g_wkt_l[DD*DD];
__device__ bf16 g_wvt_h[DD*DD],  g_wvt_l[DD*DD];
__device__ bf16 g_wot_h[DD*DD],  g_wot_l[DD*DD];
__device__ bf16 g_w1t_h[DD*MLPD], g_w1t_l[DD*MLPD];
__device__ bf16 g_w2t_h[MLPD*DD], g_w2t_l[MLPD*DD];
__device__ float g_ckv  [NCHUNKS_TOT*DHH*DHH];
__device__ float g_cks  [NCHUNKS_TOT*DHH];
__device__ float g_kvpre[NCHUNKS_TOT*DHH*DHH];
__device__ float g_kspre[NCHUNKS_TOT*DHH];

// ---------------- helpers ----------------
__device__ __forceinline__ float gelu_t(float x) {
    float x3 = x * x * x;
    float t = tanhf(0.7978845608028654f * (x + 0.044715f * x3));
    return 0.5f * x * (1.0f + t);
}
__device__ __forceinline__ unsigned pkbf(float a, float b) {
    __nv_bfloat162 t = __floats2bfloat162_rn(a, b);
    return *reinterpret_cast<unsigned*>(&t);
}
__device__ __forceinline__ uint32_t s2u(const void* p) {
    return (uint32_t)__cvta_generic_to_shared(p);
}
__device__ __forceinline__ void cpa16(uint32_t s, const void* g) {
    asm volatile("cp.async.cg.shared.global [%0], [%1], 16;" :: "r"(s), "l"(g));
}
#define CPA_COMMIT() asm volatile("cp.async.commit_group;" ::: "memory")
#define CPA_WAIT0()  asm volatile("cp.async.wait_group 0;" ::: "memory")

__device__ __forceinline__ void ldsm4(uint32_t& r0, uint32_t& r1, uint32_t& r2,
                                      uint32_t& r3, uint32_t a) {
    asm volatile("ldmatrix.sync.aligned.m8n8.x4.shared.b16 {%0,%1,%2,%3}, [%4];"
                 : "=r"(r0), "=r"(r1), "=r"(r2), "=r"(r3) : "r"(a));
}
__device__ __forceinline__ void ldsm2(uint32_t& r0, uint32_t& r1, uint32_t a) {
    asm volatile("ldmatrix.sync.aligned.m8n8.x2.shared.b16 {%0,%1}, [%2];"
                 : "=r"(r0), "=r"(r1) : "r"(a));
}
__device__ __forceinline__ void hmma(float* c, const uint32_t* a, const uint32_t* b) {
    asm volatile(
        "mma.sync.aligned.m16n8k16.row.col.f32.bf16.bf16.f32 "
        "{%0,%1,%2,%3}, {%4,%5,%6,%7}, {%8,%9}, {%0,%1,%2,%3};"
        : "+f"(c[0]), "+f"(c[1]), "+f"(c[2]), "+f"(c[3])
        : "r"(a[0]), "r"(a[1]), "r"(a[2]), "r"(a[3]), "r"(b[0]), "r"(b[1]));
}

// ---------------- weight transpose + bf16 split: W[K,N] -> Th/Tl[N,K] ----------------
__global__ void __launch_bounds__(256)
wsplit_t(const float* __restrict__ W, bf16* __restrict__ Th, bf16* __restrict__ Tl,
         int K, int N)
{
    __shared__ float t[32][33];
    int n0 = blockIdx.x * 32, k0 = blockIdx.y * 32;
    int tx = threadIdx.x & 31, ty = threadIdx.x >> 5;
#pragma unroll
    for (int r = 0; r < 4; r++) {
        int k = k0 + ty + r * 8;
        t[ty + r * 8][tx] = W[(size_t)k * N + n0 + tx];
    }
    __syncthreads();
#pragma unroll
    for (int r = 0; r < 4; r++) {
        int n = n0 + ty + r * 8;
        float vv = t[tx][ty + r * 8];
        bf16 h = __float2bfloat16_rn(vv);
        Th[(size_t)n * K + k0 + tx] = h;
        Tl[(size_t)n * K + k0 + tx] = __float2bfloat16_rn(vv - __bfloat162float(h));
    }
}

// ---------------- LayerNorm -> split bf16 ----------------
__global__ void __launch_bounds__(256)
ln_kernel(const float* __restrict__ x, const float* __restrict__ sc,
          const float* __restrict__ bi, bf16* __restrict__ yh, bf16* __restrict__ yl)
{
    int row = blockIdx.x;
    int t = threadIdx.x;
    const float4* xr = (const float4*)(x + (size_t)row * DD);
    float4 v = xr[t];
    float s  = v.x + v.y + v.z + v.w;
    float ss = v.x*v.x + v.y*v.y + v.z*v.z + v.w*v.w;
#pragma unroll
    for (int o = 16; o > 0; o >>= 1) {
        s  += __shfl_xor_sync(0xffffffffu, s,  o);
        ss += __shfl_xor_sync(0xffffffffu, ss, o);
    }
    __shared__ float sh[16];
    int w = t >> 5, l = t & 31;
    if (l == 0) { sh[w] = s; sh[8 + w] = ss; }
    __syncthreads();
    if (t < 32) {
        s  = (t < 8) ? sh[t]     : 0.f;
        ss = (t < 8) ? sh[8 + t] : 0.f;
#pragma unroll
        for (int o = 4; o > 0; o >>= 1) {
            s  += __shfl_xor_sync(0xffffffffu, s,  o);
            ss += __shfl_xor_sync(0xffffffffu, ss, o);
        }
        if (t == 0) { sh[0] = s; sh[8] = ss; }
    }
    __syncthreads();
    float mean = sh[0] * (1.0f / (float)DD);
    float var  = sh[8] * (1.0f / (float)DD) - mean * mean;
    float rs = rsqrtf(var + 1e-6f);
    float4 scv = ((const float4*)sc)[t];
    float4 biv = ((const float4*)bi)[t];
    float o0 = (v.x - mean) * rs * scv.x + biv.x;
    float o1 = (v.y - mean) * rs * scv.y + biv.y;
    float o2 = (v.z - mean) * rs * scv.z + biv.z;
    float o3 = (v.w - mean) * rs * scv.w + biv.w;
    float h0 = __bfloat162float(__float2bfloat16_rn(o0));
    float h1 = __bfloat162float(__float2bfloat16_rn(o1));
    float h2 = __bfloat162float(__float2bfloat16_rn(o2));
    float h3 = __bfloat162float(__float2bfloat16_rn(o3));
    size_t base = (size_t)row * DD + t * 4;
    *(uint2*)(yh + base) = make_uint2(pkbf(h0, h1), pkbf(h2, h3));
    *(uint2*)(yl + base) = make_uint2(pkbf(o0 - h0, o1 - h1), pkbf(o2 - h2, o3 - h3));
}

// ---------------- mma.sync split-bf16 GEMM, 128x128 tile, BK=32, double-buffered ----------------
// EPI: 0 = plain fp32 ; 1 = relu+eps fp32 ; 2 = +res fp32 ;
//      3 = +bias, gelu -> split bf16 ; 4 = +bias +res fp32
#define BKK        32
#define ROWSTRIDE  40                      // bf16 elems per smem row (80B, conflict-free ldmatrix)
#define MAT_B      (128*ROWSTRIDE*2)       // 10240 bytes per matrix per stage
#define STAGE_B    (4*MAT_B)               // 40960 bytes per stage
#define GEMM_SMEM_BYTES (2*STAGE_B)        // 81920

template <int EPI>
__global__ void __launch_bounds__(256)
mma_gemm(const bf16* __restrict__ Ah, const bf16* __restrict__ Al,
         const bf16* __restrict__ Bh, const bf16* __restrict__ Bl,
         float* __restrict__ C, bf16* __restrict__ Ch, bf16* __restrict__ Cl,
         const float* __restrict__ bias, const float* __restrict__ res,
         int M, int N, int K)
{
    extern __shared__ bf16 smbuf[];
    uint32_t sb = s2u(smbuf);
    int tid = threadIdx.x, lane = tid & 31, wid = tid >> 5;
    int wm = wid >> 2, wn = wid & 3;              // 2 x 4 warp grid
    int m0 = blockIdx.y * 128, n0 = blockIdx.x * 128;

    float acc[4][4][4];
#pragma unroll
    for (int f = 0; f < 4; f++)
#pragma unroll
        for (int g = 0; g < 4; g++)
#pragma unroll
            for (int e = 0; e < 4; e++) acc[f][g][e] = 0.f;

    // stage loader: 128 rows x 32 cols of each of Ah/Al/Bh/Bl via cp.async
    auto load_stage = [&](int kt, int st) {
        int koff = kt * BKK;
        uint32_t s0 = sb + (uint32_t)st * STAGE_B;
#pragma unroll
        for (int r = 0; r < 2; r++) {
            int e = tid + 256 * r;                // 0..511
            int row = e >> 2, q = e & 3;
            uint32_t so = (uint32_t)(row * ROWSTRIDE + q * 8) * 2;
            size_t ga = (size_t)(m0 + row) * K + koff + q * 8;
            size_t gb = (size_t)(n0 + row) * K + koff + q * 8;
            cpa16(s0 + 0 * MAT_B + so, Ah + ga);
            cpa16(s0 + 1 * MAT_B + so, Al + ga);
            cpa16(s0 + 2 * MAT_B + so, Bh + gb);
            cpa16(s0 + 3 * MAT_B + so, Bl + gb);
        }
    };

    load_stage(0, 0);
    CPA_COMMIT();
    CPA_WAIT0();
    __syncthreads();

    const int KT = K / BKK;
    for (int kt = 0; kt < KT; ++kt) {
        int st = kt & 1;
        if (kt + 1 < KT) { load_stage(kt + 1, st ^ 1); CPA_COMMIT(); }

        uint32_t sA = sb + (uint32_t)st * STAGE_B;
        uint32_t sB = sA + 2 * MAT_B;
#pragma unroll
        for (int ks = 0; ks < 2; ++ks) {
            int kb = ks * 16;
            uint32_t ah[4][4], al[4][4];
#pragma unroll
            for (int f = 0; f < 4; f++) {
                int row = wm * 64 + f * 16 + (lane & 7) + ((lane >> 3) & 1) * 8;
                int col = kb + ((lane >> 4) << 3);
                uint32_t ad = sA + (uint32_t)(row * ROWSTRIDE + col) * 2;
                ldsm4(ah[f][0], ah[f][1], ah[f][2], ah[f][3], ad);
                ldsm4(al[f][0], al[f][1], al[f][2], al[f][3], ad + MAT_B);
            }
#pragma unroll
            for (int g = 0; g < 4; g++) {
                int l2 = lane & 15;
                int nrow = wn * 32 + g * 8 + (l2 & 7);
                int col = kb + ((l2 >> 3) << 3);
                uint32_t bd = sB + (uint32_t)(nrow * ROWSTRIDE + col) * 2;
                uint32_t bh[2], bl[2];
                ldsm2(bh[0], bh[1], bd);
                ldsm2(bl[0], bl[1], bd + MAT_B);
#pragma unroll
                for (int f = 0; f < 4; f++) {
                    hmma(acc[f][g], ah[f], bh);
                    hmma(acc[f][g], ah[f], bl);
                    hmma(acc[f][g], al[f], bh);
                }
            }
        }
        if (kt + 1 < KT) CPA_WAIT0();
        __syncthreads();
    }

    // ---- epilogue: regs -> smem float stage -> coalesced global stores ----
    float* stg = (float*)smbuf;                   // 128 x 132 floats = 67584 B
#pragma unroll
    for (int f = 0; f < 4; f++) {
        int mrow = wm * 64 + f * 16 + (lane >> 2);
#pragma unroll
        for (int g = 0; g < 4; g++) {
            int ncol = wn * 32 + g * 8 + (lane & 3) * 2;
            stg[(mrow    ) * 132 + ncol    ] = acc[f][g][0];
            stg[(mrow    ) * 132 + ncol + 1] = acc[f][g][1];
            stg[(mrow + 8) * 132 + ncol    ] = acc[f][g][2];
            stg[(mrow + 8) * 132 + ncol + 1] = acc[f][g][3];
        }
    }
    __syncthreads();

#pragma unroll
    for (int r = 0; r < 16; r++) {
        int e = tid + 256 * r;
        int row = e >> 5, q = e & 31;
        float4 o = *(float4*)&stg[row * 132 + q * 4];
        int grow = m0 + row, gcol = n0 + q * 4;
        size_t gi = (size_t)grow * N + gcol;

        if (EPI == 0) {
            *(float4*)(C + gi) = o;
        } else if (EPI == 1) {
            o.x = fmaxf(o.x, 0.f) + 1e-3f;
            o.y = fmaxf(o.y, 0.f) + 1e-3f;
            o.z = fmaxf(o.z, 0.f) + 1e-3f;
            o.w = fmaxf(o.w, 0.f) + 1e-3f;
            *(float4*)(C + gi) = o;
        } else if (EPI == 2) {
            float4 rr = *(const float4*)(res + gi);
            o.x += rr.x; o.y += rr.y; o.z += rr.z; o.w += rr.w;
            *(float4*)(C + gi) = o;
        } else if (EPI == 3) {
            float4 bb = *(const float4*)(bias + gcol);
            o.x = gelu_t(o.x + bb.x); o.y = gelu_t(o.y + bb.y);
            o.z = gelu_t(o.z + bb.z); o.w = gelu_t(o.w + bb.w);
            float h0 = __bfloat162float(__float2bfloat16_rn(o.x));
            float h1 = __bfloat162float(__float2bfloat16_rn(o.y));
            float h2 = __bfloat162float(__float2bfloat16_rn(o.z));
            float h3 = __bfloat162float(__float2bfloat16_rn(o.w));
            *(uint2*)(Ch + gi) = make_uint2(pkbf(h0, h1), pkbf(h2, h3));
            *(uint2*)(Cl + gi) = make_uint2(pkbf(o.x - h0, o.y - h1), pkbf(o.z - h2, o.w - h3));
        } else {  // EPI == 4
            float4 bb = *(const float4*)(bias + gcol);
            float4 rr = *(const float4*)(res + gi);
            o.x += bb.x + rr.x; o.y += bb.y + rr.y;
            o.z += bb.z + rr.z; o.w += bb.w + rr.w;
            *(float4*)(C + gi) = o;
        }
    }
}

// ---------------- attention pass A: per-chunk KV = phiK^T V and ksum ----------------
__global__ void __launch_bounds__(256)
attn_chunk_kernel(const float* __restrict__ Kk, const float* __restrict__ V,
                  float* __restrict__ ckv, float* __restrict__ cks)
{
    __shared__ float sK[64][64];
    __shared__ float sV[64][64];
    int g = blockIdx.x;
    int c = g & 15, bh = g >> 4;
    int h = bh & 15, b = bh >> 4;
    int row0 = b * SS + c * CCH;
    int colBase = h * 64;
    int t = threadIdx.x;
    int m = t >> 2;
    int d0 = (t & 3) * 16;

    float acc[16];
#pragma unroll
    for (int w = 0; w < 16; w++) acc[w] = 0.f;
    float ks = 0.f;

    for (int half = 0; half < 2; ++half) {
#pragma unroll
        for (int r = 0; r < 16; r++) {
            int e = t + 256 * r;
            int s = e >> 6, d = e & 63;
            size_t gi = (size_t)(row0 + half * 64 + s) * DD + colBase + d;
            sK[s][d] = Kk[gi];
            sV[s][d] = V[gi];
        }
        __syncthreads();
        for (int s = 0; s < 64; s++) {
            float kk = sK[s][m];
            if ((t & 3) == 0) ks += kk;
            const float* vr = &sV[s][d0];
#pragma unroll
            for (int w = 0; w < 4; w++) {
                float4 vv = *(const float4*)(vr + 4 * w);
                acc[4 * w + 0] += kk * vv.x;
                acc[4 * w + 1] += kk * vv.y;
                acc[4 * w + 2] += kk * vv.z;
                acc[4 * w + 3] += kk * vv.w;
            }
        }
        __syncthreads();
    }
    float* op = ckv + (size_t)g * (DHH * DHH) + m * 64 + d0;
#pragma unroll
    for (int w = 0; w < 4; w++)
        *(float4*)(op + 4 * w) = make_float4(acc[4*w], acc[4*w+1], acc[4*w+2], acc[4*w+3]);
    if ((t & 3) == 0) cks[g * 64 + m] = ks;
}

// ---------------- attention pass B: exclusive prefix over chunks ----------------
__global__ void __launch_bounds__(256)
attn_scan_kernel(const float* __restrict__ ckv, const float* __restrict__ cks,
                 float* __restrict__ kvpre, float* __restrict__ kspre)
{
    int bh = blockIdx.x;
    int t = threadIdx.x;
    float run[16];
#pragma unroll
    for (int r = 0; r < 16; r++) run[r] = 0.f;
    float krun = 0.f;
    for (int c = 0; c < NCH; c++) {
        size_t base = ((size_t)bh * NCH + c) * (DHH * DHH);
#pragma unroll
        for (int r = 0; r < 16; r++) {
            int e = t + 256 * r;
            kvpre[base + e] = run[r];
            run[r] += ckv[base + e];
        }
        if (t < 64) {
            int kb = (bh * NCH + c) * 64 + t;
            kspre[kb] = krun;
            krun += cks[kb];
        }
    }
}

// ---------------- attention pass C: per-chunk causal output -> split bf16 ----------------
#define ATTN_SMEM_FLOATS (64*132 + 64*132 + 128*68 + 64*68 + 64 + 128*132)
#define ATTN_SMEM_BYTES  (ATTN_SMEM_FLOATS * 4)

__global__ void __launch_bounds__(256)
attn_out_kernel(const float* __restrict__ Q, const float* __restrict__ Kk,
                const float* __restrict__ V, const float* __restrict__ kvpre,
                const float* __restrict__ kspre,
                bf16* __restrict__ ah, bf16* __restrict__ al)
{
    extern __shared__ float sm[];
    float* sQt = sm;
    float* sKt = sQt + 64 * 132;
    float* sV  = sKt + 64 * 132;
    float* sKV = sV  + 128 * 68;
    float* sKs = sKV + 64 * 68;
    float* sA  = sKs + 64;

    int g = blockIdx.x;
    int c = g & 15, bh = g >> 4;
    int h = bh & 15, b = bh >> 4;
    int row0 = b * SS + c * CCH;
    int colBase = h * 64;
    int t = threadIdx.x;

#pragma unroll
    for (int r = 0; r < 32; r++) {
        int e = t + 256 * r;
        int s = e >> 6, m = e & 63;
        size_t gi = (size_t)(row0 + s) * DD + colBase + m;
        sQt[m * 132 + s] = Q[gi];
        sKt[m * 132 + s] = Kk[gi];
        sV[s * 68 + m]   = V[gi];
    }
#pragma unroll
    for (int r = 0; r < 16; r++) {
        int e = t + 256 * r;
        sKV[(e >> 6) * 68 + (e & 63)] = kvpre[(size_t)g * (DHH * DHH) + e];
    }
    if (t < 64) sKs[t] = kspre[g * 64 + t];
    __syncthreads();

    {
        int ty = t >> 4, tx = t & 15;
        float accA[8][8];
#pragma unroll
        for (int i = 0; i < 8; i++)
#pragma unroll
            for (int j = 0; j < 8; j++) accA[i][j] = 0.f;
        for (int kk = 0; kk < 64; kk++) {
            const float* qr = &sQt[kk * 132 + ty * 8];
            float4 q0 = *(const float4*)qr;
            float4 q1 = *(const float4*)(qr + 4);
            const float* kr = &sKt[kk * 132 + tx * 8];
            float4 k0 = *(const float4*)kr;
            float4 k1 = *(const float4*)(kr + 4);
            float qa[8] = { q0.x, q0.y, q0.z, q0.w, q1.x, q1.y, q1.z, q1.w };
            float kb[8] = { k0.x, k0.y, k0.z, k0.w, k1.x, k1.y, k1.z, k1.w };
#pragma unroll
            for (int i = 0; i < 8; i++)
#pragma unroll
                for (int j = 0; j < 8; j++) accA[i][j] += qa[i] * kb[j];
        }
        int i0 = ty * 8, j0 = tx * 8;
#pragma unroll
        for (int i = 0; i < 8; i++)
#pragma unroll
            for (int j = 0; j < 8; j++)
                sA[(i0 + i) * 132 + (j0 + j)] = (j0 + j <= i0 + i) ? accA[i][j] : 0.f;
    }
    __syncthreads();

    {
        int i = t >> 1;
        int d0 = (t & 1) * 32;
        float acc[32];
#pragma unroll
        for (int w = 0; w < 32; w++) acc[w] = 0.f;
        float den = 0.f;
        for (int j = 0; j < 128; j++) {
            float a = sA[i * 132 + j];
            den += a;
            const float* vr = &sV[j * 68 + d0];
#pragma unroll
            for (int w = 0; w < 8; w++) {
                float4 vv = *(const float4*)(vr + 4 * w);
                acc[4 * w + 0] += a * vv.x;
                acc[4 * w + 1] += a * vv.y;
                acc[4 * w + 2] += a * vv.z;
                acc[4 * w + 3] += a * vv.w;
            }
        }
        for (int m = 0; m < 64; m++) {
            float p = sQt[m * 132 + i];
            den += p * sKs[m];
            const float* kr = &sKV[m * 68 + d0];
#pragma unroll
            for (int w = 0; w < 8; w++) {
                float4 vv = *(const float4*)(kr + 4 * w);
                acc[4 * w + 0] += p * vv.x;
                acc[4 * w + 1] += p * vv.y;
                acc[4 * w + 2] += p * vv.z;
                acc[4 * w + 3] += p * vv.w;
            }
        }
        float inv = 1.0f / den;
        size_t base = (size_t)(row0 + i) * DD + colBase + d0;
#pragma unroll
        for (int w = 0; w < 8; w++) {
            float o0 = acc[4*w+0] * inv, o1 = acc[4*w+1] * inv;
            float o2 = acc[4*w+2] * inv, o3 = acc[4*w+3] * inv;
            float h0 = __bfloat162float(__float2bfloat16_rn(o0));
            float h1 = __bfloat162float(__float2bfloat16_rn(o1));
            float h2 = __bfloat162float(__float2bfloat16_rn(o2));
            float h3 = __bfloat162float(__float2bfloat16_rn(o3));
            *(uint2*)(ah + base + 4 * w) = make_uint2(pkbf(h0, h1), pkbf(h2, h3));
            *(uint2*)(al + base + 4 * w) = make_uint2(pkbf(o0 - h0, o1 - h1), pkbf(o2 - h2, o3 - h3));
        }
    }
}

// ---------------- launch ----------------
extern "C" void kernel_launch(void* const* d_in, const int* in_sizes, int n_in,
                              void* d_out, int out_size)
{
    const float* inputs = (const float*)d_in[0];
    const float* ln1s   = (const float*)d_in[1];
    const float* ln1b   = (const float*)d_in[2];
    const float* wq     = (const float*)d_in[3];
    const float* wk     = (const float*)d_in[4];
    const float* wv     = (const float*)d_in[5];
    const float* wo     = (const float*)d_in[6];
    const float* ln2s   = (const float*)d_in[7];
    const float* ln2b   = (const float*)d_in[8];
    const float* w1     = (const float*)d_in[9];
    const float* b1     = (const float*)d_in[10];
    const float* w2     = (const float*)d_in[11];
    const float* b2     = (const float*)d_in[12];
    float* out = (float*)d_out;

    float *q, *k, *v, *x2, *ckv, *cks, *kvpre, *kspre;
    bf16 *xh, *xl, *ah, *al, *yh, *yl, *h1h, *h1l;
    bf16 *wqt_h, *wqt_l, *wkt_h, *wkt_l, *wvt_h, *wvt_l, *wot_h, *wot_l;
    bf16 *w1t_h, *w1t_l, *w2t_h, *w2t_l;
    cudaGetSymbolAddress((void**)&q,     g_q);
    cudaGetSymbolAddress((void**)&k,     g_k);
    cudaGetSymbolAddress((void**)&v,     g_v);
    cudaGetSymbolAddress((void**)&x2,    g_x2);
    cudaGetSymbolAddress((void**)&ckv,   g_ckv);
    cudaGetSymbolAddress((void**)&cks,   g_cks);
    cudaGetSymbolAddress((void**)&kvpre, g_kvpre);
    cudaGetSymbolAddress((void**)&kspre, g_kspre);
    cudaGetSymbolAddress((void**)&xh,  g_xh);  cudaGetSymbolAddress((void**)&xl,  g_xl);
    cudaGetSymbolAddress((void**)&ah,  g_ah);  cudaGetSymbolAddress((void**)&al,  g_al);
    cudaGetSymbolAddress((void**)&yh,  g_yh);  cudaGetSymbolAddress((void**)&yl,  g_yl);
    cudaGetSymbolAddress((void**)&h1h, g_h1h); cudaGetSymbolAddress((void**)&h1l, g_h1l);
    cudaGetSymbolAddress((void**)&wqt_h, g_wqt_h); cudaGetSymbolAddress((void**)&wqt_l, g_wqt_l);
    cudaGetSymbolAddress((void**)&wkt_h, g_wkt_h); cudaGetSymbolAddress((void**)&wkt_l, g_wkt_l);
    cudaGetSymbolAddress((void**)&wvt_h, g_wvt_h); cudaGetSymbolAddress((void**)&wvt_l, g_wvt_l);
    cudaGetSymbolAddress((void**)&wot_h, g_wot_h); cudaGetSymbolAddress((void**)&wot_l, g_wot_l);
    cudaGetSymbolAddress((void**)&w1t_h, g_w1t_h); cudaGetSymbolAddress((void**)&w1t_l, g_w1t_l);
    cudaGetSymbolAddress((void**)&w2t_h, g_w2t_h); cudaGetSymbolAddress((void**)&w2t_l, g_w2t_l);

    cudaFuncSetAttribute(attn_out_kernel,
                         cudaFuncAttributeMaxDynamicSharedMemorySize, ATTN_SMEM_BYTES);
    cudaFuncSetAttribute(mma_gemm<0>, cudaFuncAttributeMaxDynamicSharedMemorySize, GEMM_SMEM_BYTES);
    cudaFuncSetAttribute(mma_gemm<1>, cudaFuncAttributeMaxDynamicSharedMemorySize, GEMM_SMEM_BYTES);
    cudaFuncSetAttribute(mma_gemm<2>, cudaFuncAttributeMaxDynamicSharedMemorySize, GEMM_SMEM_BYTES);
    cudaFuncSetAttribute(mma_gemm<3>, cudaFuncAttributeMaxDynamicSharedMemorySize, GEMM_SMEM_BYTES);
    cudaFuncSetAttribute(mma_gemm<4>, cudaFuncAttributeMaxDynamicSharedMemorySize, GEMM_SMEM_BYTES);

    // 0) weight transpose + split (Bt[N,K] bf16 hi/lo)
    wsplit_t<<<dim3(DD / 32, DD / 32), 256>>>(wq, wqt_h, wqt_l, DD, DD);
    wsplit_t<<<dim3(DD / 32, DD / 32), 256>>>(wk, wkt_h, wkt_l, DD, DD);
    wsplit_t<<<dim3(DD / 32, DD / 32), 256>>>(wv, wvt_h, wvt_l, DD, DD);
    wsplit_t<<<dim3(DD / 32, DD / 32), 256>>>(wo, wot_h, wot_l, DD, DD);
    wsplit_t<<<dim3(MLPD / 32, DD / 32), 256>>>(w1, w1t_h, w1t_l, DD, MLPD);
    wsplit_t<<<dim3(DD / 32, MLPD / 32), 256>>>(w2, w2t_h, w2t_l, MLPD, DD);

    // 1) LN1 -> split bf16
    ln_kernel<<<ROWS, 256>>>(inputs, ln1s, ln1b, xh, xl);
    // 2) QKV projections (phi = relu+eps fused into Q,K; V plain)
    mma_gemm<1><<<dim3(DD / 128, ROWS / 128), 256, GEMM_SMEM_BYTES>>>(
        xh, xl, wqt_h, wqt_l, q, nullptr, nullptr, nullptr, nullptr, ROWS, DD, DD);
    mma_gemm<1><<<dim3(DD / 128, ROWS / 128), 256, GEMM_SMEM_BYTES>>>(
        xh, xl, wkt_h, wkt_l, k, nullptr, nullptr, nullptr, nullptr, ROWS, DD, DD);
    mma_gemm<0><<<dim3(DD / 128, ROWS / 128), 256, GEMM_SMEM_BYTES>>>(
        xh, xl, wvt_h, wvt_l, v, nullptr, nullptr, nullptr, nullptr, ROWS, DD, DD);
    // 3) chunked causal linear attention
    attn_chunk_kernel<<<NCHUNKS_TOT, 256>>>(k, v, ckv, cks);
    attn_scan_kernel<<<BHN, 256>>>(ckv, cks, kvpre, kspre);
    attn_out_kernel<<<NCHUNKS_TOT, 256, ATTN_SMEM_BYTES>>>(q, k, v, kvpre, kspre, ah, al);
    // 4) output projection + residual -> x2
    mma_gemm<2><<<dim3(DD / 128, ROWS / 128), 256, GEMM_SMEM_BYTES>>>(
        ah, al, wot_h, wot_l, x2, nullptr, nullptr, nullptr, inputs, ROWS, DD, DD);
    // 5) LN2 -> split bf16
    ln_kernel<<<ROWS, 256>>>(x2, ln2s, ln2b, yh, yl);
    // 6) MLP
    mma_gemm<3><<<dim3(MLPD / 128, ROWS / 128), 256, GEMM_SMEM_BYTES>>>(
        yh, yl, w1t_h, w1t_l, nullptr, h1h, h1l, b1, nullptr, ROWS, MLPD, DD);
    mma_gemm<4><<<dim3(DD / 128, ROWS / 128), 256, GEMM_SMEM_BYTES>>>(
        h1h, h1l, w2t_h, w2t_l, out, nullptr, nullptr, b2, x2, ROWS, DD, MLPD);
}